// round 4
// baseline (speedup 1.0000x reference)
#include <cuda_runtime.h>
#include <math.h>
#include <stdint.h>

#define Bx 4
#define Nx 8192
#define Cx 64
#define Dx 128
#define Sx 2048
#define Kx 32

// Scratch (no allocations allowed): packed points (x,y,z,|p|^2) and knn indices
__device__ float4 g_pts[Bx * Nx];
__device__ int    g_knn[Bx * Sx * Kx];

__device__ __forceinline__ float gelu_f(float x) {
    return 0.5f * x * (1.0f + erff(x * 0.70710678118654752440f));
}

// JAX linspace(0, 8191, 2048): step = fl(s/2047); out = fl(8191*step)
// (convex-combination formula with start=0). jnp.round = round-half-even.
// Correctly-rounded intrinsics so --use_fast_math cannot perturb this.
__device__ __forceinline__ int sample_idx(int s) {
    float q = __fdiv_rn((float)s, 2047.0f);
    return __float2int_rn(__fmul_rn(8191.0f, q));
}

// ---------------------------------------------------------------------------
// Kernel A: pack points + c2, and write sampled coords to d_out
// ---------------------------------------------------------------------------
__global__ void prep_kernel(const float* __restrict__ coords,
                            float* __restrict__ out_sampled) {
    int t = blockIdx.x * blockDim.x + threadIdx.x;
    if (t < Bx * Nx) {
        float x = coords[3 * t + 0];
        float y = coords[3 * t + 1];
        float z = coords[3 * t + 2];
        g_pts[t] = make_float4(x, y, z, fmaf(z, z, fmaf(y, y, x * x)));
    }
    if (t < Bx * Sx) {
        int b = t / Sx;
        int s = t - b * Sx;
        int sidx = sample_idx(s);
        const float* c = coords + 3 * ((size_t)b * Nx + sidx);
        out_sampled[3 * t + 0] = c[0];
        out_sampled[3 * t + 1] = c[1];
        out_sampled[3 * t + 2] = c[2];
    }
}

// ---------------------------------------------------------------------------
// Kernel B: kNN — one thread per query, whole batch's points in shared (128KB)
// Exact fp32 (reference einsum with contraction dim 3 is an exact-fp32 fusion).
// ---------------------------------------------------------------------------
__device__ __forceinline__ void sift_down(float* hd, int* hi, int i) {
    float v = hd[i];
    int vi = hi[i];
    while (true) {
        int l = 2 * i + 1;
        if (l >= Kx) break;
        int m = l;
        int r = l + 1;
        if (r < Kx && hd[r] > hd[l]) m = r;
        if (hd[m] <= v) break;
        hd[i] = hd[m]; hi[i] = hi[m];
        i = m;
    }
    hd[i] = v; hi[i] = vi;
}

__global__ void knn_kernel() {
    extern __shared__ float4 sh[];  // Nx float4 = 128KB
    int b = blockIdx.x >> 5;                         // 32 blocks per batch
    int s = ((blockIdx.x & 31) << 6) + threadIdx.x;  // 64 queries per block

    for (int i = threadIdx.x; i < Nx; i += 64)
        sh[i] = g_pts[b * Nx + i];
    __syncthreads();

    int sidx = sample_idx(s);
    float4 sp = sh[sidx];
    float sx = sp.x, sy = sp.y, sz = sp.z, s2 = sp.w;

    float hd[Kx];
    int hi[Kx];
#pragma unroll
    for (int n = 0; n < Kx; n++) {
        float4 p = sh[n];
        float dot = fmaf(sx, p.x, fmaf(sy, p.y, sz * p.z));
        hd[n] = fmaf(-2.0f, dot, s2 + p.w);
        hi[n] = n;
    }
    for (int i = Kx / 2 - 1; i >= 0; --i) sift_down(hd, hi, i);
    float hmax = hd[0];

    // Scan remaining candidates, 8-wide batches for ILP against LDS latency
    for (int n0 = Kx; n0 < Nx; n0 += 8) {
        float d2v[8];
#pragma unroll
        for (int u = 0; u < 8; u++) {
            float4 p = sh[n0 + u];
            float dot = fmaf(sx, p.x, fmaf(sy, p.y, sz * p.z));
            d2v[u] = fmaf(-2.0f, dot, s2 + p.w);
        }
#pragma unroll
        for (int u = 0; u < 8; u++) {
            if (d2v[u] < hmax) {
                hd[0] = d2v[u];
                hi[0] = n0 + u;
                sift_down(hd, hi, 0);
                hmax = hd[0];
            }
        }
    }

    int* o = g_knn + (size_t)(b * Sx + s) * Kx;
#pragma unroll
    for (int j = 0; j < Kx; j++) o[j] = hi[j];
}

// ---------------------------------------------------------------------------
// Kernel C: gather + MLP (67->128 gelu -> 128 gelu) + max-pool over k
// 256 threads/block = two 128-thread subgroups sharing the weight smem.
// Exact fp32 throughout; fp32 accumulation; bias added after the dot.
// ---------------------------------------------------------------------------
// Shared layout (floats):
//   [0)      W1s  67*128 = 8576
//   [8576)   b1s  128
//   [8704)   W2s  128*128 = 16384
//   [25088)  b2s  128
//   [25216 + wg*6800):
//       gT   67*32  = 2144   (gT[c][j])
//       h1T  128*36 = 4608   (h1T[c][j], stride 36 for alignment)
//       nidx 32 ints, samp 3 floats (rest pad)
#define SMEM_FLOATS (25216 + 2 * 6800)

__global__ __launch_bounds__(256, 1) void mlp_kernel(
    const float* __restrict__ features,
    const float* __restrict__ W1, const float* __restrict__ b1,
    const float* __restrict__ W2, const float* __restrict__ b2,
    float* __restrict__ out_pooled) {
    extern __shared__ float sm[];
    float* W1s = sm;
    float* b1s = sm + 8576;
    float* W2s = sm + 8704;
    float* b2s = sm + 25088;

    int tid = threadIdx.x;
    for (int i = tid; i < 67 * Dx; i += 256) W1s[i] = W1[i];
    for (int i = tid; i < Dx * Dx; i += 256) W2s[i] = W2[i];
    if (tid < Dx) { b1s[tid] = b1[tid]; b2s[tid] = b2[tid]; }
    __syncthreads();

    int wg = tid >> 7;
    int lt = tid & 127;
    int group = blockIdx.x * 2 + wg;   // = b*Sx + s
    int b = group >> 11;

    float* gT   = sm + 25216 + wg * 6800;
    float* h1T  = gT + 2144;
    int*   nidx = (int*)(h1T + 4608);
    float* samp = (float*)(nidx + 32);

    if (lt < 32) nidx[lt] = g_knn[(size_t)group * Kx + lt];
    if (lt == 0) {
        int s = group & 2047;
        float4 p = g_pts[b * Nx + sample_idx(s)];
        samp[0] = p.x; samp[1] = p.y; samp[2] = p.z;
    }
    asm volatile("bar.sync %0, 128;" :: "r"(wg + 1) : "memory");

    // Build gT[c][j]: c<3 rel coords, c>=3 features
    {
        int j = lt >> 2, seg = lt & 3;
        int ni = nidx[j];
        const float4* frow =
            (const float4*)(features + ((size_t)b * Nx + ni) * Cx) + seg * 4;
#pragma unroll
        for (int q = 0; q < 4; q++) {
            float4 v = frow[q];
            int c = 3 + seg * 16 + q * 4;
            gT[(c + 0) * 32 + j] = v.x;
            gT[(c + 1) * 32 + j] = v.y;
            gT[(c + 2) * 32 + j] = v.z;
            gT[(c + 3) * 32 + j] = v.w;
        }
        if (seg == 0) {
            float4 p = g_pts[b * Nx + ni];
            gT[0 * 32 + j] = p.x - samp[0];
            gT[1 * 32 + j] = p.y - samp[1];
            gT[2 * 32 + j] = p.z - samp[2];
        }
    }
    asm volatile("bar.sync %0, 128;" :: "r"(wg + 1) : "memory");

    int d = lt;  // output channel
    float acc[32];

    // Layer 1: h1[j][d] = gelu( (sum_c gT[c][j]*W1[c][d]) + b1[d] )
#pragma unroll
    for (int j = 0; j < 32; j++) acc[j] = 0.0f;
    for (int c = 0; c < 67; c++) {
        float w = W1s[c * Dx + d];
        const float4* g4 = (const float4*)(gT + c * 32);
#pragma unroll
        for (int jq = 0; jq < 8; jq++) {
            float4 v = g4[jq];
            acc[4 * jq + 0] = fmaf(v.x, w, acc[4 * jq + 0]);
            acc[4 * jq + 1] = fmaf(v.y, w, acc[4 * jq + 1]);
            acc[4 * jq + 2] = fmaf(v.z, w, acc[4 * jq + 2]);
            acc[4 * jq + 3] = fmaf(v.w, w, acc[4 * jq + 3]);
        }
    }
    {
        float bv = b1s[d];
        float4* row = (float4*)(h1T + d * 36);  // h1T[d][j], thread d owns row d
#pragma unroll
        for (int jq = 0; jq < 8; jq++) {
            float4 v;
            v.x = gelu_f(acc[4 * jq + 0] + bv);
            v.y = gelu_f(acc[4 * jq + 1] + bv);
            v.z = gelu_f(acc[4 * jq + 2] + bv);
            v.w = gelu_f(acc[4 * jq + 3] + bv);
            row[jq] = v;
        }
    }
    asm volatile("bar.sync %0, 128;" :: "r"(wg + 1) : "memory");

    // Layer 2: h2[j][d] = gelu( (sum_c h1T[c][j]*W2[c][d]) + b2[d] ); pool max_j
#pragma unroll
    for (int j = 0; j < 32; j++) acc[j] = 0.0f;
    for (int c = 0; c < Dx; c++) {
        float w = W2s[c * Dx + d];
        const float4* h4 = (const float4*)(h1T + c * 36);
#pragma unroll
        for (int jq = 0; jq < 8; jq++) {
            float4 v = h4[jq];
            acc[4 * jq + 0] = fmaf(v.x, w, acc[4 * jq + 0]);
            acc[4 * jq + 1] = fmaf(v.y, w, acc[4 * jq + 1]);
            acc[4 * jq + 2] = fmaf(v.z, w, acc[4 * jq + 2]);
            acc[4 * jq + 3] = fmaf(v.w, w, acc[4 * jq + 3]);
        }
    }
    float bv = b2s[d];
    float m = -INFINITY;
#pragma unroll
    for (int j = 0; j < 32; j++) m = fmaxf(m, gelu_f(acc[j] + bv));
    out_pooled[(size_t)group * Dx + d] = m;
}

// ---------------------------------------------------------------------------
extern "C" void kernel_launch(void* const* d_in, const int* in_sizes, int n_in,
                              void* d_out, int out_size) {
    (void)in_sizes; (void)n_in; (void)out_size;
    const float* coords   = (const float*)d_in[0];
    const float* features = (const float*)d_in[1];
    const float* W1 = (const float*)d_in[2];
    const float* b1 = (const float*)d_in[3];
    const float* W2 = (const float*)d_in[4];
    const float* b2 = (const float*)d_in[5];

    float* out = (float*)d_out;
    float* out_sampled = out;                       // (B,S,3)
    float* out_pooled  = out + (size_t)Bx * Sx * 3; // (B,S,128)

    prep_kernel<<<(Bx * Nx + 255) / 256, 256>>>(coords, out_sampled);

    cudaFuncSetAttribute(knn_kernel,
                         cudaFuncAttributeMaxDynamicSharedMemorySize,
                         Nx * (int)sizeof(float4));
    knn_kernel<<<Bx * 32, 64, Nx * sizeof(float4)>>>();

    cudaFuncSetAttribute(mlp_kernel,
                         cudaFuncAttributeMaxDynamicSharedMemorySize,
                         SMEM_FLOATS * (int)sizeof(float));
    mlp_kernel<<<Bx * Sx / 2, 256, SMEM_FLOATS * sizeof(float)>>>(
        features, W1, b1, W2, b2, out_pooled);
}

// round 5
// speedup vs baseline: 1.0734x; 1.0734x over previous
#include <cuda_runtime.h>
#include <math.h>
#include <stdint.h>

#define Bx 4
#define Nx 8192
#define Cx 64
#define Dx 128
#define Sx 2048
#define Kx 32

// Scratch (no allocations allowed): packed points (x,y,z,|p|^2) and knn indices
__device__ float4 g_pts[Bx * Nx];
__device__ int    g_knn[Bx * Sx * Kx];

// ---------------------------------------------------------------------------
// Branchless GELU via Abramowitz-Stegun 7.1.26 erf (|abs err| <= ~2e-7)
// ---------------------------------------------------------------------------
__device__ __forceinline__ float gelu_f(float x) {
    float z = fabsf(x) * 0.70710678118654752440f;
    float den = fmaf(0.3275911f, z, 1.0f);
    float t;
    asm("rcp.approx.f32 %0, %1;" : "=f"(t) : "f"(den));
    float poly = t * fmaf(t, fmaf(t, fmaf(t, fmaf(t, 1.061405429f, -1.453152027f),
                                          1.421413741f), -0.284496736f), 0.254829592f);
    float ex = __expf(-z * z);
    float e = fmaf(-poly, ex, 1.0f);   // erf(|x|/sqrt2)
    float s = copysignf(e, x);
    return 0.5f * x * (1.0f + s);
}

// Packed f32x2 helpers (sm_103a FFMA2 path; IEEE-exact per lane)
__device__ __forceinline__ uint64_t pack2(float a, float b) {
    uint64_t r;
    asm("mov.b64 %0, {%1, %2};" : "=l"(r) : "f"(a), "f"(b));
    return r;
}
__device__ __forceinline__ void fma2(uint64_t& d, uint64_t a, uint64_t b) {
    asm("fma.rn.f32x2 %0, %1, %2, %3;" : "=l"(d) : "l"(a), "l"(b), "l"(d));
}
__device__ __forceinline__ float2 unpack2(uint64_t v) {
    float2 r;
    asm("mov.b64 {%0, %1}, %2;" : "=f"(r.x), "=f"(r.y) : "l"(v));
    return r;
}

// JAX linspace(0, 8191, 2048): step = fl(s/2047); out = fl(8191*step).
// jnp.round = round-half-even. Correctly-rounded intrinsics.
__device__ __forceinline__ int sample_idx(int s) {
    float q = __fdiv_rn((float)s, 2047.0f);
    return __float2int_rn(__fmul_rn(8191.0f, q));
}

// ---------------------------------------------------------------------------
// Kernel A: pack points + c2, and write sampled coords to d_out
// ---------------------------------------------------------------------------
__global__ void prep_kernel(const float* __restrict__ coords,
                            float* __restrict__ out_sampled) {
    int t = blockIdx.x * blockDim.x + threadIdx.x;
    if (t < Bx * Nx) {
        float x = coords[3 * t + 0];
        float y = coords[3 * t + 1];
        float z = coords[3 * t + 2];
        g_pts[t] = make_float4(x, y, z, fmaf(z, z, fmaf(y, y, x * x)));
    }
    if (t < Bx * Sx) {
        int b = t / Sx;
        int s = t - b * Sx;
        int sidx = sample_idx(s);
        const float* c = coords + 3 * ((size_t)b * Nx + sidx);
        out_sampled[3 * t + 0] = c[0];
        out_sampled[3 * t + 1] = c[1];
        out_sampled[3 * t + 2] = c[2];
    }
}

// ---------------------------------------------------------------------------
// Kernel B: kNN — one thread per query, whole batch's points in shared (128KB)
// Exact fp32.
// ---------------------------------------------------------------------------
__device__ __forceinline__ void sift_down(float* hd, int* hi, int i) {
    float v = hd[i];
    int vi = hi[i];
    while (true) {
        int l = 2 * i + 1;
        if (l >= Kx) break;
        int m = l;
        int r = l + 1;
        if (r < Kx && hd[r] > hd[l]) m = r;
        if (hd[m] <= v) break;
        hd[i] = hd[m]; hi[i] = hi[m];
        i = m;
    }
    hd[i] = v; hi[i] = vi;
}

__global__ void knn_kernel() {
    extern __shared__ float4 sh[];  // Nx float4 = 128KB
    int b = blockIdx.x >> 5;                         // 32 blocks per batch
    int s = ((blockIdx.x & 31) << 6) + threadIdx.x;  // 64 queries per block

    for (int i = threadIdx.x; i < Nx; i += 64)
        sh[i] = g_pts[b * Nx + i];
    __syncthreads();

    int sidx = sample_idx(s);
    float4 sp = sh[sidx];
    float sx = sp.x, sy = sp.y, sz = sp.z, s2 = sp.w;

    float hd[Kx];
    int hi[Kx];
#pragma unroll
    for (int n = 0; n < Kx; n++) {
        float4 p = sh[n];
        float dot = fmaf(sx, p.x, fmaf(sy, p.y, sz * p.z));
        hd[n] = fmaf(-2.0f, dot, s2 + p.w);
        hi[n] = n;
    }
    for (int i = Kx / 2 - 1; i >= 0; --i) sift_down(hd, hi, i);
    float hmax = hd[0];

    for (int n0 = Kx; n0 < Nx; n0 += 8) {
        float d2v[8];
#pragma unroll
        for (int u = 0; u < 8; u++) {
            float4 p = sh[n0 + u];
            float dot = fmaf(sx, p.x, fmaf(sy, p.y, sz * p.z));
            d2v[u] = fmaf(-2.0f, dot, s2 + p.w);
        }
#pragma unroll
        for (int u = 0; u < 8; u++) {
            if (d2v[u] < hmax) {
                hd[0] = d2v[u];
                hi[0] = n0 + u;
                sift_down(hd, hi, 0);
                hmax = hd[0];
            }
        }
    }

    int* o = g_knn + (size_t)(b * Sx + s) * Kx;
#pragma unroll
    for (int j = 0; j < Kx; j++) o[j] = hi[j];
}

// ---------------------------------------------------------------------------
// Kernel C: gather + MLP (67->128 gelu -> 128 gelu) + max-pool over k
// 512 threads/block = four 128-thread subgroups sharing the weight smem.
// Packed f32x2 FMA (exact); branchless AS-erf gelu; layer-2 gelu via
// max/min unimodality trick (2 gelus instead of 32).
// ---------------------------------------------------------------------------
// Shared layout (floats):
//   [0)      W1s  67*128 = 8576
//   [8576)   b1s  128
//   [8704)   W2s  128*128 = 16384
//   [25088)  b2s  128
//   [25216 + wg*6800):
//       gT   67*32  = 2144   (gT[c][j])
//       h1T  128*36 = 4608   (h1T[c][j], stride 36 for alignment)
//       nidx 32 ints, samp 3 floats (rest pad)
#define NSG 4
#define SMEM_FLOATS (25216 + NSG * 6800)

__global__ __launch_bounds__(128 * NSG, 1) void mlp_kernel(
    const float* __restrict__ features,
    const float* __restrict__ W1, const float* __restrict__ b1,
    const float* __restrict__ W2, const float* __restrict__ b2,
    float* __restrict__ out_pooled) {
    extern __shared__ float sm[];
    float* W1s = sm;
    float* b1s = sm + 8576;
    float* W2s = sm + 8704;
    float* b2s = sm + 25088;

    int tid = threadIdx.x;
    for (int i = tid; i < 67 * Dx; i += 128 * NSG) W1s[i] = W1[i];
    for (int i = tid; i < Dx * Dx; i += 128 * NSG) W2s[i] = W2[i];
    if (tid < Dx) { b1s[tid] = b1[tid]; b2s[tid] = b2[tid]; }
    __syncthreads();

    int wg = tid >> 7;
    int lt = tid & 127;
    int group = blockIdx.x * NSG + wg;   // = b*Sx + s
    int b = group >> 11;

    float* gT   = sm + 25216 + wg * 6800;
    float* h1T  = gT + 2144;
    int*   nidx = (int*)(h1T + 4608);
    float* samp = (float*)(nidx + 32);

    if (lt < 32) nidx[lt] = g_knn[(size_t)group * Kx + lt];
    if (lt == 0) {
        int s = group & 2047;
        float4 p = g_pts[b * Nx + sample_idx(s)];
        samp[0] = p.x; samp[1] = p.y; samp[2] = p.z;
    }
    asm volatile("bar.sync %0, 128;" :: "r"(wg + 1) : "memory");

    // Build gT[c][j]: c<3 rel coords, c>=3 features
    {
        int j = lt >> 2, seg = lt & 3;
        int ni = nidx[j];
        const float4* frow =
            (const float4*)(features + ((size_t)b * Nx + ni) * Cx) + seg * 4;
#pragma unroll
        for (int q = 0; q < 4; q++) {
            float4 v = frow[q];
            int c = 3 + seg * 16 + q * 4;
            gT[(c + 0) * 32 + j] = v.x;
            gT[(c + 1) * 32 + j] = v.y;
            gT[(c + 2) * 32 + j] = v.z;
            gT[(c + 3) * 32 + j] = v.w;
        }
        if (seg == 0) {
            float4 p = g_pts[b * Nx + ni];
            gT[0 * 32 + j] = p.x - samp[0];
            gT[1 * 32 + j] = p.y - samp[1];
            gT[2 * 32 + j] = p.z - samp[2];
        }
    }
    asm volatile("bar.sync %0, 128;" :: "r"(wg + 1) : "memory");

    int d = lt;            // output channel
    uint64_t acc2[16];     // 32 fp32 accumulators as 16 f32x2 pairs (j, j+1)

    // Layer 1: h1[j][d] = gelu( (sum_c gT[c][j]*W1[c][d]) + b1[d] )
#pragma unroll
    for (int i = 0; i < 16; i++) acc2[i] = 0ull;
    for (int c = 0; c < 67; c++) {
        uint64_t w2;
        {
            float w = W1s[c * Dx + d];
            w2 = pack2(w, w);
        }
        const ulonglong2* g2 = (const ulonglong2*)(gT + c * 32);
#pragma unroll
        for (int q = 0; q < 8; q++) {
            ulonglong2 v = g2[q];
            fma2(acc2[2 * q + 0], v.x, w2);
            fma2(acc2[2 * q + 1], v.y, w2);
        }
    }
    {
        float bv = b1s[d];
        float4* row = (float4*)(h1T + d * 36);  // h1T[d][j], thread d owns row d
#pragma unroll
        for (int q = 0; q < 8; q++) {
            float2 a0 = unpack2(acc2[2 * q + 0]);
            float2 a1 = unpack2(acc2[2 * q + 1]);
            float4 v;
            v.x = gelu_f(a0.x + bv);
            v.y = gelu_f(a0.y + bv);
            v.z = gelu_f(a1.x + bv);
            v.w = gelu_f(a1.y + bv);
            row[q] = v;
        }
    }
    asm volatile("bar.sync %0, 128;" :: "r"(wg + 1) : "memory");

    // Layer 2: z[j][d] = (sum_c h1T[c][j]*W2[c][d]) + b2[d]
    // pooled[d] = max_j gelu(z) = max(gelu(max_j z), gelu(min_j z))  [unimodal]
#pragma unroll
    for (int i = 0; i < 16; i++) acc2[i] = 0ull;
    for (int c = 0; c < Dx; c++) {
        uint64_t w2;
        {
            float w = W2s[c * Dx + d];
            w2 = pack2(w, w);
        }
        const ulonglong2* h2 = (const ulonglong2*)(h1T + c * 36);
#pragma unroll
        for (int q = 0; q < 8; q++) {
            ulonglong2 v = h2[q];
            fma2(acc2[2 * q + 0], v.x, w2);
            fma2(acc2[2 * q + 1], v.y, w2);
        }
    }
    float zmax = -INFINITY, zmin = INFINITY;
#pragma unroll
    for (int i = 0; i < 16; i++) {
        float2 a = unpack2(acc2[i]);
        zmax = fmaxf(zmax, fmaxf(a.x, a.y));
        zmin = fminf(zmin, fminf(a.x, a.y));
    }
    float bv = b2s[d];
    float m = fmaxf(gelu_f(zmax + bv), gelu_f(zmin + bv));
    out_pooled[(size_t)group * Dx + d] = m;
}

// ---------------------------------------------------------------------------
extern "C" void kernel_launch(void* const* d_in, const int* in_sizes, int n_in,
                              void* d_out, int out_size) {
    (void)in_sizes; (void)n_in; (void)out_size;
    const float* coords   = (const float*)d_in[0];
    const float* features = (const float*)d_in[1];
    const float* W1 = (const float*)d_in[2];
    const float* b1 = (const float*)d_in[3];
    const float* W2 = (const float*)d_in[4];
    const float* b2 = (const float*)d_in[5];

    float* out = (float*)d_out;
    float* out_sampled = out;                       // (B,S,3)
    float* out_pooled  = out + (size_t)Bx * Sx * 3; // (B,S,128)

    prep_kernel<<<(Bx * Nx + 255) / 256, 256>>>(coords, out_sampled);

    cudaFuncSetAttribute(knn_kernel,
                         cudaFuncAttributeMaxDynamicSharedMemorySize,
                         Nx * (int)sizeof(float4));
    knn_kernel<<<Bx * 32, 64, Nx * sizeof(float4)>>>();

    cudaFuncSetAttribute(mlp_kernel,
                         cudaFuncAttributeMaxDynamicSharedMemorySize,
                         SMEM_FLOATS * (int)sizeof(float));
    mlp_kernel<<<Bx * Sx / NSG, 128 * NSG, SMEM_FLOATS * sizeof(float)>>>(
        features, W1, b1, W2, b2, out_pooled);
}

// round 7
// speedup vs baseline: 2.5640x; 2.3888x over previous
#include <cuda_runtime.h>
#include <math.h>
#include <stdint.h>

#define Bx 4
#define Nx 8192
#define Cx 64
#define Dx 128
#define Sx 2048
#define Kx 32

// Scratch (no allocations allowed): packed points (x,y,z,|p|^2) and knn indices
__device__ float4 g_pts[Bx * Nx];
__device__ int    g_knn[Bx * Sx * Kx];

// ---------------------------------------------------------------------------
// Branchless GELU via Abramowitz-Stegun 7.1.26 erf (|abs err| <= ~2e-7)
// ---------------------------------------------------------------------------
__device__ __forceinline__ float gelu_f(float x) {
    float z = fabsf(x) * 0.70710678118654752440f;
    float den = fmaf(0.3275911f, z, 1.0f);
    float t;
    asm("rcp.approx.f32 %0, %1;" : "=f"(t) : "f"(den));
    float poly = t * fmaf(t, fmaf(t, fmaf(t, fmaf(t, 1.061405429f, -1.453152027f),
                                          1.421413741f), -0.284496736f), 0.254829592f);
    float ex = __expf(-z * z);
    float e = fmaf(-poly, ex, 1.0f);   // erf(|x|/sqrt2)
    float s = copysignf(e, x);
    return 0.5f * x * (1.0f + s);
}

// Packed f32x2 helpers (sm_103a FFMA2 path; IEEE-exact per lane)
__device__ __forceinline__ uint64_t pack2(float a, float b) {
    uint64_t r;
    asm("mov.b64 %0, {%1, %2};" : "=l"(r) : "f"(a), "f"(b));
    return r;
}
__device__ __forceinline__ void fma2(uint64_t& d, uint64_t a, uint64_t b) {
    asm("fma.rn.f32x2 %0, %1, %2, %3;" : "=l"(d) : "l"(a), "l"(b), "l"(d));
}
__device__ __forceinline__ float2 unpack2(uint64_t v) {
    float2 r;
    asm("mov.b64 {%0, %1}, %2;" : "=f"(r.x), "=f"(r.y) : "l"(v));
    return r;
}

// JAX linspace(0, 8191, 2048): step = fl(s/2047); out = fl(8191*step).
// jnp.round = round-half-even. Correctly-rounded intrinsics.
__device__ __forceinline__ int sample_idx(int s) {
    float q = __fdiv_rn((float)s, 2047.0f);
    return __float2int_rn(__fmul_rn(8191.0f, q));
}

// ---------------------------------------------------------------------------
// Kernel A: pack points + c2, and write sampled coords to d_out
// ---------------------------------------------------------------------------
__global__ void prep_kernel(const float* __restrict__ coords,
                            float* __restrict__ out_sampled) {
    int t = blockIdx.x * blockDim.x + threadIdx.x;
    if (t < Bx * Nx) {
        float x = coords[3 * t + 0];
        float y = coords[3 * t + 1];
        float z = coords[3 * t + 2];
        g_pts[t] = make_float4(x, y, z, fmaf(z, z, fmaf(y, y, x * x)));
    }
    if (t < Bx * Sx) {
        int b = t / Sx;
        int s = t - b * Sx;
        int sidx = sample_idx(s);
        const float* c = coords + 3 * ((size_t)b * Nx + sidx);
        out_sampled[3 * t + 0] = c[0];
        out_sampled[3 * t + 1] = c[1];
        out_sampled[3 * t + 2] = c[2];
    }
}

// ---------------------------------------------------------------------------
// Kernel B: warp-cooperative kNN. One warp per query; running top-32 lives
// distributed one (value,idx) per lane in registers. Insertion = replace the
// warp's lex-max element, re-reduce max via shfl butterfly. ~180 insertions
// per query expected. No local memory, no divergent serial heap walks.
// Semantics match jax.lax.top_k: keep 32 lex-smallest (d2, idx).
// ---------------------------------------------------------------------------
__global__ __launch_bounds__(512, 1) void knn_kernel() {
    extern __shared__ float4 sh[];  // Nx float4 = 128KB
    int b = blockIdx.x >> 7;                              // 128 blocks per batch
    int s = ((blockIdx.x & 127) << 4) + (threadIdx.x >> 5);  // 16 warps = 16 queries
    int lane = threadIdx.x & 31;

    for (int i = threadIdx.x; i < Nx; i += 512)
        sh[i] = g_pts[b * Nx + i];
    __syncthreads();

    int sidx = sample_idx(s);
    float4 sp = sh[sidx];
    float sx = sp.x, sy = sp.y, sz = sp.z, s2 = sp.w;

    // Seed: lane holds candidate `lane`
    float held;
    int heldIdx = lane;
    {
        float4 p = sh[lane];
        held = fmaf(-2.0f, fmaf(sx, p.x, fmaf(sy, p.y, sz * p.z)), s2 + p.w);
    }

    float hmax;
    int maxlane;
    {
        float m = held; int mi = heldIdx; int ml = lane;
#pragma unroll
        for (int off = 16; off; off >>= 1) {
            float om = __shfl_xor_sync(0xffffffffu, m, off);
            int omi = __shfl_xor_sync(0xffffffffu, mi, off);
            int oml = __shfl_xor_sync(0xffffffffu, ml, off);
            if (om > m || (om == m && omi > mi)) { m = om; mi = omi; ml = oml; }
        }
        hmax = m; maxlane = ml;
    }

    for (int n0 = Kx; n0 < Nx; n0 += 32) {
        float4 p = sh[n0 + lane];
        float d = fmaf(-2.0f, fmaf(sx, p.x, fmaf(sy, p.y, sz * p.z)), s2 + p.w);
        unsigned qm = __ballot_sync(0xffffffffu, d < hmax);
        while (qm) {
            int src = __ffs(qm) - 1;
            qm &= qm - 1;
            float v = __shfl_sync(0xffffffffu, d, src);
            if (v < hmax) {   // re-check against shrunken threshold
                if (lane == maxlane) { held = v; heldIdx = n0 + src; }
                float m = held; int mi = heldIdx; int ml = lane;
#pragma unroll
                for (int off = 16; off; off >>= 1) {
                    float om = __shfl_xor_sync(0xffffffffu, m, off);
                    int omi = __shfl_xor_sync(0xffffffffu, mi, off);
                    int oml = __shfl_xor_sync(0xffffffffu, ml, off);
                    if (om > m || (om == m && omi > mi)) { m = om; mi = omi; ml = oml; }
                }
                hmax = m; maxlane = ml;
            }
        }
    }

    g_knn[(size_t)(b * Sx + s) * Kx + lane] = heldIdx;
}

// ---------------------------------------------------------------------------
// Kernel C: gather + MLP (67->128 gelu -> 128 gelu) + max-pool over k
// 512 threads/block = four 128-thread subgroups sharing the weight smem.
// Packed f32x2 FMA (exact); branchless AS-erf gelu; layer-2 gelu via
// max/min unimodality trick (2 gelus instead of 32).
// ---------------------------------------------------------------------------
#define NSG 4
#define SMEM_FLOATS (25216 + NSG * 6800)

__global__ __launch_bounds__(128 * NSG, 1) void mlp_kernel(
    const float* __restrict__ features,
    const float* __restrict__ W1, const float* __restrict__ b1,
    const float* __restrict__ W2, const float* __restrict__ b2,
    float* __restrict__ out_pooled) {
    extern __shared__ float sm[];
    float* W1s = sm;
    float* b1s = sm + 8576;
    float* W2s = sm + 8704;
    float* b2s = sm + 25088;

    int tid = threadIdx.x;
    for (int i = tid; i < 67 * Dx; i += 128 * NSG) W1s[i] = W1[i];
    for (int i = tid; i < Dx * Dx; i += 128 * NSG) W2s[i] = W2[i];
    if (tid < Dx) { b1s[tid] = b1[tid]; b2s[tid] = b2[tid]; }
    __syncthreads();

    int wg = tid >> 7;
    int lt = tid & 127;
    int group = blockIdx.x * NSG + wg;   // = b*Sx + s
    int b = group >> 11;

    float* gT   = sm + 25216 + wg * 6800;
    float* h1T  = gT + 2144;
    int*   nidx = (int*)(h1T + 4608);
    float* samp = (float*)(nidx + 32);

    if (lt < 32) nidx[lt] = g_knn[(size_t)group * Kx + lt];
    if (lt == 0) {
        int s = group & 2047;
        float4 p = g_pts[b * Nx + sample_idx(s)];
        samp[0] = p.x; samp[1] = p.y; samp[2] = p.z;
    }
    asm volatile("bar.sync %0, 128;" :: "r"(wg + 1) : "memory");

    // Build gT[c][j]: c<3 rel coords, c>=3 features
    {
        int j = lt >> 2, seg = lt & 3;
        int ni = nidx[j];
        const float4* frow =
            (const float4*)(features + ((size_t)b * Nx + ni) * Cx) + seg * 4;
#pragma unroll
        for (int q = 0; q < 4; q++) {
            float4 v = frow[q];
            int c = 3 + seg * 16 + q * 4;
            gT[(c + 0) * 32 + j] = v.x;
            gT[(c + 1) * 32 + j] = v.y;
            gT[(c + 2) * 32 + j] = v.z;
            gT[(c + 3) * 32 + j] = v.w;
        }
        if (seg == 0) {
            float4 p = g_pts[b * Nx + ni];
            gT[0 * 32 + j] = p.x - samp[0];
            gT[1 * 32 + j] = p.y - samp[1];
            gT[2 * 32 + j] = p.z - samp[2];
        }
    }
    asm volatile("bar.sync %0, 128;" :: "r"(wg + 1) : "memory");

    int d = lt;            // output channel
    uint64_t acc2[16];     // 32 fp32 accumulators as 16 f32x2 pairs

    // Layer 1: h1[j][d] = gelu( (sum_c gT[c][j]*W1[c][d]) + b1[d] )
#pragma unroll
    for (int i = 0; i < 16; i++) acc2[i] = 0ull;
    for (int c = 0; c < 67; c++) {
        uint64_t w2;
        {
            float w = W1s[c * Dx + d];
            w2 = pack2(w, w);
        }
        const ulonglong2* g2 = (const ulonglong2*)(gT + c * 32);
#pragma unroll
        for (int q = 0; q < 8; q++) {
            ulonglong2 v = g2[q];
            fma2(acc2[2 * q + 0], v.x, w2);
            fma2(acc2[2 * q + 1], v.y, w2);
        }
    }
    {
        float bv = b1s[d];
        float4* row = (float4*)(h1T + d * 36);  // h1T[d][j], thread d owns row d
#pragma unroll
        for (int q = 0; q < 8; q++) {
            float2 a0 = unpack2(acc2[2 * q + 0]);
            float2 a1 = unpack2(acc2[2 * q + 1]);
            float4 v;
            v.x = gelu_f(a0.x + bv);
            v.y = gelu_f(a0.y + bv);
            v.z = gelu_f(a1.x + bv);
            v.w = gelu_f(a1.y + bv);
            row[q] = v;
        }
    }
    asm volatile("bar.sync %0, 128;" :: "r"(wg + 1) : "memory");

    // Layer 2: z[j][d] = (sum_c h1T[c][j]*W2[c][d]) + b2[d]
    // pooled[d] = max(gelu(max_j z), gelu(min_j z))  [gelu unimodal]
#pragma unroll
    for (int i = 0; i < 16; i++) acc2[i] = 0ull;
    for (int c = 0; c < Dx; c++) {
        uint64_t w2;
        {
            float w = W2s[c * Dx + d];
            w2 = pack2(w, w);
        }
        const ulonglong2* h2 = (const ulonglong2*)(h1T + c * 36);
#pragma unroll
        for (int q = 0; q < 8; q++) {
            ulonglong2 v = h2[q];
            fma2(acc2[2 * q + 0], v.x, w2);
            fma2(acc2[2 * q + 1], v.y, w2);
        }
    }
    float zmax = -INFINITY, zmin = INFINITY;
#pragma unroll
    for (int i = 0; i < 16; i++) {
        float2 a = unpack2(acc2[i]);
        zmax = fmaxf(zmax, fmaxf(a.x, a.y));
        zmin = fminf(zmin, fminf(a.x, a.y));
    }
    float bv = b2s[d];
    float m = fmaxf(gelu_f(zmax + bv), gelu_f(zmin + bv));
    out_pooled[(size_t)group * Dx + d] = m;
}

// ---------------------------------------------------------------------------
extern "C" void kernel_launch(void* const* d_in, const int* in_sizes, int n_in,
                              void* d_out, int out_size) {
    (void)in_sizes; (void)n_in; (void)out_size;
    const float* coords   = (const float*)d_in[0];
    const float* features = (const float*)d_in[1];
    const float* W1 = (const float*)d_in[2];
    const float* b1 = (const float*)d_in[3];
    const float* W2 = (const float*)d_in[4];
    const float* b2 = (const float*)d_in[5];

    float* out = (float*)d_out;
    float* out_sampled = out;                       // (B,S,3)
    float* out_pooled  = out + (size_t)Bx * Sx * 3; // (B,S,128)

    prep_kernel<<<(Bx * Nx + 255) / 256, 256>>>(coords, out_sampled);

    cudaFuncSetAttribute(knn_kernel,
                         cudaFuncAttributeMaxDynamicSharedMemorySize,
                         Nx * (int)sizeof(float4));
    knn_kernel<<<Bx * Sx / 16, 512, Nx * sizeof(float4)>>>();

    cudaFuncSetAttribute(mlp_kernel,
                         cudaFuncAttributeMaxDynamicSharedMemorySize,
                         SMEM_FLOATS * (int)sizeof(float));
    mlp_kernel<<<Bx * Sx / NSG, 128 * NSG, SMEM_FLOATS * sizeof(float)>>>(
        features, W1, b1, W2, b2, out_pooled);
}

// round 8
// speedup vs baseline: 3.2547x; 1.2694x over previous
#include <cuda_runtime.h>
#include <math.h>
#include <stdint.h>

#define Bx 4
#define Nx 8192
#define Cx 64
#define Dx 128
#define Sx 2048
#define Kx 32
#define HALF 4096

// Scratch: partial top-32 keys per (query, half) and final knn indices
__device__ unsigned long long g_part[Bx * Sx * 2 * Kx];   // 4 MB
__device__ int g_knn[Bx * Sx * Kx];

// ---------------------------------------------------------------------------
// Branchless GELU via Abramowitz-Stegun 7.1.26 erf (|abs err| <= ~2e-7)
// ---------------------------------------------------------------------------
__device__ __forceinline__ float gelu_f(float x) {
    float z = fabsf(x) * 0.70710678118654752440f;
    float den = fmaf(0.3275911f, z, 1.0f);
    float t;
    asm("rcp.approx.f32 %0, %1;" : "=f"(t) : "f"(den));
    float poly = t * fmaf(t, fmaf(t, fmaf(t, fmaf(t, 1.061405429f, -1.453152027f),
                                          1.421413741f), -0.284496736f), 0.254829592f);
    float ex = __expf(-z * z);
    float e = fmaf(-poly, ex, 1.0f);   // erf(|x|/sqrt2)
    float s = copysignf(e, x);
    return 0.5f * x * (1.0f + s);
}

// Packed f32x2 helpers (sm_103a FFMA2 path; IEEE-exact per lane)
__device__ __forceinline__ uint64_t pack2(float a, float b) {
    uint64_t r;
    asm("mov.b64 %0, {%1, %2};" : "=l"(r) : "f"(a), "f"(b));
    return r;
}
__device__ __forceinline__ void fma2(uint64_t& d, uint64_t a, uint64_t b) {
    asm("fma.rn.f32x2 %0, %1, %2, %3;" : "=l"(d) : "l"(a), "l"(b), "l"(d));
}
__device__ __forceinline__ float2 unpack2(uint64_t v) {
    float2 r;
    asm("mov.b64 {%0, %1}, %2;" : "=f"(r.x), "=f"(r.y) : "l"(v));
    return r;
}

// JAX linspace(0, 8191, 2048): step = fl(s/2047); out = fl(8191*step).
// jnp.round = round-half-even. Correctly-rounded intrinsics.
__device__ __forceinline__ int sample_idx(int s) {
    float q = __fdiv_rn((float)s, 2047.0f);
    return __float2int_rn(__fmul_rn(8191.0f, q));
}

// Monotone float->uint mapping (total order == float order for non-NaN)
__device__ __forceinline__ unsigned ordf(float f) {
    unsigned u = __float_as_uint(f);
    return u ^ ((u >> 31) ? 0xffffffffu : 0x80000000u);
}

// Recompute (hmax, maxlane) over the warp's held (d2, idx) set.
// Eviction order: max d2, tie -> max idx (= the element top_k would drop first).
__device__ __forceinline__ void recompute_max(float held, int heldIdx,
                                              float& hmax, int& maxlane) {
    unsigned hk = ordf(held);
    unsigned mk = __reduce_max_sync(0xffffffffu, hk);
    unsigned mm = __ballot_sync(0xffffffffu, hk == mk);
    if (__popc(mm) > 1) {
        unsigned cand = (hk == mk) ? (unsigned)heldIdx : 0u;
        unsigned mi = __reduce_max_sync(0xffffffffu, cand);
        mm = __ballot_sync(0xffffffffu, (hk == mk) && ((unsigned)heldIdx == mi));
    }
    maxlane = __ffs(mm) - 1;
    hmax = __shfl_sync(0xffffffffu, held, maxlane);
}

// ---------------------------------------------------------------------------
// Kernel 1: partial kNN. 1024 blocks: (query-group, half). Each warp keeps the
// top-32 of its 4096-candidate half, one (d2,idx) per lane in registers.
// Insertion: replace warp lex-max element, recompute max via REDUX.
// ---------------------------------------------------------------------------
__global__ __launch_bounds__(512, 2) void knn_part_kernel(
    const float* __restrict__ coords) {
    extern __shared__ float4 sh[];   // HALF float4 = 64KB
    int blk = blockIdx.x;
    int half = blk & 1;
    int qg = blk >> 1;               // 0..511
    int b = qg >> 7;
    int warp = threadIdx.x >> 5;
    int s = ((qg & 127) << 4) + warp;
    int lane = threadIdx.x & 31;
    int base = half * HALF;

    // Build packed tile (x,y,z,|p|^2) from coords
    for (int i = threadIdx.x; i < HALF; i += 512) {
        const float* c = coords + 3 * ((size_t)b * Nx + base + i);
        float x = c[0], y = c[1], z = c[2];
        sh[i] = make_float4(x, y, z, fmaf(z, z, fmaf(y, y, x * x)));
    }
    __syncthreads();

    // Query point (same c2 formula)
    float sx, sy, sz, s2;
    {
        const float* c = coords + 3 * ((size_t)b * Nx + sample_idx(s));
        sx = c[0]; sy = c[1]; sz = c[2];
        s2 = fmaf(sz, sz, fmaf(sy, sy, sx * sx));
    }

    // Seed with the half's first 32 candidates
    float held;
    int heldIdx = base + lane;
    {
        float4 p = sh[lane];
        held = fmaf(-2.0f, fmaf(sx, p.x, fmaf(sy, p.y, sz * p.z)), s2 + p.w);
    }
    float hmax;
    int maxlane;
    recompute_max(held, heldIdx, hmax, maxlane);

    for (int n0 = Kx; n0 < HALF; n0 += 32) {
        float4 p = sh[n0 + lane];
        float d = fmaf(-2.0f, fmaf(sx, p.x, fmaf(sy, p.y, sz * p.z)), s2 + p.w);
        unsigned qm = __ballot_sync(0xffffffffu, d < hmax);
        while (qm) {
            int src = __ffs(qm) - 1;
            qm &= qm - 1;
            float v = __shfl_sync(0xffffffffu, d, src);
            if (v < hmax) {          // re-check vs shrunken threshold
                if (lane == maxlane) { held = v; heldIdx = base + n0 + src; }
                recompute_max(held, heldIdx, hmax, maxlane);
            }
        }
    }

    unsigned hk = ordf(held);
    g_part[((size_t)(b * Sx + s) * 2 + half) * Kx + lane] =
        ((unsigned long long)hk << 32) | (unsigned)heldIdx;
}

// ---------------------------------------------------------------------------
// Kernel 2: merge two partial top-32 sets -> top-32 (warp bitonic sort of 64
// u64 keys, 2 per lane). Also writes the sampled-coords output.
// ---------------------------------------------------------------------------
__global__ __launch_bounds__(512, 2) void knn_merge_kernel(
    const float* __restrict__ coords, float* __restrict__ out_sampled) {
    int q = blockIdx.x * 16 + (threadIdx.x >> 5);
    int lane = threadIdx.x & 31;

    const unsigned long long* part = g_part + (size_t)q * 2 * Kx;
    unsigned long long a = part[lane];        // pos = lane
    unsigned long long bb = part[32 + lane];  // pos = lane + 32

    // Bitonic sort 64 elements ascending
#pragma unroll
    for (int k = 2; k <= 64; k <<= 1) {
#pragma unroll
        for (int j = k >> 1; j > 0; j >>= 1) {
            if (j >= 32) {
                // k==64, j==32: partner is the other slot of the same lane
                unsigned long long lo = a < bb ? a : bb;
                unsigned long long hi = a < bb ? bb : a;
                a = lo; bb = hi;      // ascending everywhere at k=64
            } else {
                unsigned long long pa = __shfl_xor_sync(0xffffffffu, a, j);
                unsigned long long pb = __shfl_xor_sync(0xffffffffu, bb, j);
                bool lower = ((lane & j) == 0);
                bool upA = ((lane & k) == 0) || (k == 64);
                bool upB = (((lane + 32) & k) == 0) || (k == 64);
                bool keepMinA = (lower == upA);
                bool keepMinB = (lower == upB);
                a  = keepMinA ? (a  < pa ? a  : pa) : (a  > pa ? a  : pa);
                bb = keepMinB ? (bb < pb ? bb : pb) : (bb > pb ? bb : pb);
            }
        }
    }
    // lanes 0..31 slot-a now hold the 32 smallest keys
    g_knn[(size_t)q * Kx + lane] = (int)(a & 0xffffffffu);

    // Sampled coords output (first 24576 threads of the grid)
    int t = blockIdx.x * 512 + threadIdx.x;
    if (t < Bx * Sx * 3) {
        int idx = t / 3, comp = t - idx * 3;
        int b2 = idx >> 11, s2i = idx & 2047;
        out_sampled[t] = coords[3 * ((size_t)b2 * Nx + sample_idx(s2i)) + comp];
    }
}

// ---------------------------------------------------------------------------
// Kernel 3: gather + MLP (67->128 gelu -> 128 gelu) + max-pool over k.
// 1024 CTAs x 512 threads (4 subgroups), each CTA loops over 2 group-quads.
// ---------------------------------------------------------------------------
#define NSG 4
#define SMEM_FLOATS (25216 + NSG * 6800)

__global__ __launch_bounds__(128 * NSG, 1) void mlp_kernel(
    const float* __restrict__ coords,
    const float* __restrict__ features,
    const float* __restrict__ W1, const float* __restrict__ b1,
    const float* __restrict__ W2, const float* __restrict__ b2,
    float* __restrict__ out_pooled) {
    extern __shared__ float sm[];
    float* W1s = sm;
    float* b1s = sm + 8576;
    float* W2s = sm + 8704;
    float* b2s = sm + 25088;

    int tid = threadIdx.x;
    for (int i = tid; i < 67 * Dx; i += 128 * NSG) W1s[i] = W1[i];
    for (int i = tid; i < Dx * Dx; i += 128 * NSG) W2s[i] = W2[i];
    if (tid < Dx) { b1s[tid] = b1[tid]; b2s[tid] = b2[tid]; }
    __syncthreads();

    int wg = tid >> 7;
    int lt = tid & 127;
    int d = lt;

    float* gT   = sm + 25216 + wg * 6800;
    float* h1T  = gT + 2144;
    int*   nidx = (int*)(h1T + 4608);
    float* samp = (float*)(nidx + 32);

    for (int gq = blockIdx.x; gq < (Bx * Sx) / NSG; gq += 1024) {
        int group = gq * NSG + wg;   // = b*Sx + s
        int b = group >> 11;

        asm volatile("bar.sync %0, 128;" :: "r"(wg + 1) : "memory");
        if (lt < 32) nidx[lt] = g_knn[(size_t)group * Kx + lt];
        if (lt == 0) {
            int s = group & 2047;
            const float* c = coords + 3 * ((size_t)b * Nx + sample_idx(s));
            samp[0] = c[0]; samp[1] = c[1]; samp[2] = c[2];
        }
        asm volatile("bar.sync %0, 128;" :: "r"(wg + 1) : "memory");

        // Build gT[c][j]
        {
            int j = lt >> 2, seg = lt & 3;
            int ni = nidx[j];
            const float4* frow =
                (const float4*)(features + ((size_t)b * Nx + ni) * Cx) + seg * 4;
#pragma unroll
            for (int q = 0; q < 4; q++) {
                float4 v = frow[q];
                int c = 3 + seg * 16 + q * 4;
                gT[(c + 0) * 32 + j] = v.x;
                gT[(c + 1) * 32 + j] = v.y;
                gT[(c + 2) * 32 + j] = v.z;
                gT[(c + 3) * 32 + j] = v.w;
            }
            if (seg == 0) {
                const float* c = coords + 3 * ((size_t)b * Nx + ni);
                gT[0 * 32 + j] = c[0] - samp[0];
                gT[1 * 32 + j] = c[1] - samp[1];
                gT[2 * 32 + j] = c[2] - samp[2];
            }
        }
        asm volatile("bar.sync %0, 128;" :: "r"(wg + 1) : "memory");

        uint64_t acc2[16];

        // Layer 1
#pragma unroll
        for (int i = 0; i < 16; i++) acc2[i] = 0ull;
        for (int c = 0; c < 67; c++) {
            uint64_t w2;
            {
                float w = W1s[c * Dx + d];
                w2 = pack2(w, w);
            }
            const ulonglong2* g2 = (const ulonglong2*)(gT + c * 32);
#pragma unroll
            for (int q = 0; q < 8; q++) {
                ulonglong2 v = g2[q];
                fma2(acc2[2 * q + 0], v.x, w2);
                fma2(acc2[2 * q + 1], v.y, w2);
            }
        }
        {
            float bv = b1s[d];
            float4* row = (float4*)(h1T + d * 36);
#pragma unroll
            for (int q = 0; q < 8; q++) {
                float2 a0 = unpack2(acc2[2 * q + 0]);
                float2 a1 = unpack2(acc2[2 * q + 1]);
                float4 v;
                v.x = gelu_f(a0.x + bv);
                v.y = gelu_f(a0.y + bv);
                v.z = gelu_f(a1.x + bv);
                v.w = gelu_f(a1.y + bv);
                row[q] = v;
            }
        }
        asm volatile("bar.sync %0, 128;" :: "r"(wg + 1) : "memory");

        // Layer 2 + pool (gelu unimodal: max over j needs only max/min of z)
#pragma unroll
        for (int i = 0; i < 16; i++) acc2[i] = 0ull;
        for (int c = 0; c < Dx; c++) {
            uint64_t w2;
            {
                float w = W2s[c * Dx + d];
                w2 = pack2(w, w);
            }
            const ulonglong2* h2 = (const ulonglong2*)(h1T + c * 36);
#pragma unroll
            for (int q = 0; q < 8; q++) {
                ulonglong2 v = h2[q];
                fma2(acc2[2 * q + 0], v.x, w2);
                fma2(acc2[2 * q + 1], v.y, w2);
            }
        }
        float zmax = -INFINITY, zmin = INFINITY;
#pragma unroll
        for (int i = 0; i < 16; i++) {
            float2 a = unpack2(acc2[i]);
            zmax = fmaxf(zmax, fmaxf(a.x, a.y));
            zmin = fminf(zmin, fminf(a.x, a.y));
        }
        float bv = b2s[d];
        float m = fmaxf(gelu_f(zmax + bv), gelu_f(zmin + bv));
        out_pooled[(size_t)group * Dx + d] = m;
    }
}

// ---------------------------------------------------------------------------
extern "C" void kernel_launch(void* const* d_in, const int* in_sizes, int n_in,
                              void* d_out, int out_size) {
    (void)in_sizes; (void)n_in; (void)out_size;
    const float* coords   = (const float*)d_in[0];
    const float* features = (const float*)d_in[1];
    const float* W1 = (const float*)d_in[2];
    const float* b1 = (const float*)d_in[3];
    const float* W2 = (const float*)d_in[4];
    const float* b2 = (const float*)d_in[5];

    float* out = (float*)d_out;
    float* out_sampled = out;                       // (B,S,3)
    float* out_pooled  = out + (size_t)Bx * Sx * 3; // (B,S,128)

    cudaFuncSetAttribute(knn_part_kernel,
                         cudaFuncAttributeMaxDynamicSharedMemorySize,
                         HALF * (int)sizeof(float4));
    knn_part_kernel<<<1024, 512, HALF * sizeof(float4)>>>(coords);

    knn_merge_kernel<<<512, 512>>>(coords, out_sampled);

    cudaFuncSetAttribute(mlp_kernel,
                         cudaFuncAttributeMaxDynamicSharedMemorySize,
                         SMEM_FLOATS * (int)sizeof(float));
    mlp_kernel<<<1024, 128 * NSG, SMEM_FLOATS * sizeof(float)>>>(
        coords, features, W1, b1, W2, b2, out_pooled);
}

// round 11
// speedup vs baseline: 4.1983x; 1.2899x over previous
#include <cuda_runtime.h>
#include <math.h>
#include <stdint.h>

#define Bx 4
#define Nx 8192
#define Cx 64
#define Dx 128
#define Sx 2048
#define Kx 32
#define HALF 4096

// Scratch: partial top-32 keys per (query, half) and final knn indices
__device__ unsigned long long g_part[Bx * Sx * 2 * Kx];   // 4 MB
__device__ int g_knn[Bx * Sx * Kx];

// ---------------------------------------------------------------------------
// Math helpers
// ---------------------------------------------------------------------------
__device__ __forceinline__ float gelu_f(float x) {
    float z = fabsf(x) * 0.70710678118654752440f;
    float den = fmaf(0.3275911f, z, 1.0f);
    float t;
    asm("rcp.approx.f32 %0, %1;" : "=f"(t) : "f"(den));
    float poly = t * fmaf(t, fmaf(t, fmaf(t, fmaf(t, 1.061405429f, -1.453152027f),
                                          1.421413741f), -0.284496736f), 0.254829592f);
    float ex = __expf(-z * z);
    float e = fmaf(-poly, ex, 1.0f);
    float s = copysignf(e, x);
    return 0.5f * x * (1.0f + s);
}

__device__ __forceinline__ int sample_idx(int s) {
    float q = __fdiv_rn((float)s, 2047.0f);
    return __float2int_rn(__fmul_rn(8191.0f, q));
}

__device__ __forceinline__ unsigned ordf(float f) {
    unsigned u = __float_as_uint(f);
    return u ^ ((u >> 31) ? 0xffffffffu : 0x80000000u);
}

// tf32 hi/lo split: x ~= hi + lo, each tf32; dropped lo*lo term ~2^-22.
__device__ __forceinline__ uint32_t tf32u(float x) {
    uint32_t u;
    asm("cvt.rna.tf32.f32 %0, %1;" : "=r"(u) : "f"(x));
    return u;
}
__device__ __forceinline__ void tf32_split(float x, uint32_t& h, uint32_t& l) {
    h = tf32u(x);
    l = tf32u(x - __uint_as_float(h));
}

// m16n8k8 tf32 mma, acc in-place
__device__ __forceinline__ void mma_tf32(float* c, const uint32_t* a,
                                         const uint32_t* b) {
    asm volatile(
        "mma.sync.aligned.m16n8k8.row.col.f32.tf32.tf32.f32 "
        "{%0,%1,%2,%3}, {%4,%5,%6,%7}, {%8,%9}, {%0,%1,%2,%3};"
        : "+f"(c[0]), "+f"(c[1]), "+f"(c[2]), "+f"(c[3])
        : "r"(a[0]), "r"(a[1]), "r"(a[2]), "r"(a[3]), "r"(b[0]), "r"(b[1]));
}

__device__ __forceinline__ void recompute_max(float held, int heldIdx,
                                              float& hmax, int& maxlane) {
    unsigned hk = ordf(held);
    unsigned mk = __reduce_max_sync(0xffffffffu, hk);
    unsigned mm = __ballot_sync(0xffffffffu, hk == mk);
    if (__popc(mm) > 1) {
        unsigned cand = (hk == mk) ? (unsigned)heldIdx : 0u;
        unsigned mi = __reduce_max_sync(0xffffffffu, cand);
        mm = __ballot_sync(0xffffffffu, (hk == mk) && ((unsigned)heldIdx == mi));
    }
    maxlane = __ffs(mm) - 1;
    hmax = __shfl_sync(0xffffffffu, held, maxlane);
}

// ---------------------------------------------------------------------------
// Kernel 1: partial kNN (unchanged, passing)
// ---------------------------------------------------------------------------
__global__ __launch_bounds__(512, 2) void knn_part_kernel(
    const float* __restrict__ coords) {
    extern __shared__ float4 sh[];
    int blk = blockIdx.x;
    int half = blk & 1;
    int qg = blk >> 1;
    int b = qg >> 7;
    int warp = threadIdx.x >> 5;
    int s = ((qg & 127) << 4) + warp;
    int lane = threadIdx.x & 31;
    int base = half * HALF;

    for (int i = threadIdx.x; i < HALF; i += 512) {
        const float* c = coords + 3 * ((size_t)b * Nx + base + i);
        float x = c[0], y = c[1], z = c[2];
        sh[i] = make_float4(x, y, z, fmaf(z, z, fmaf(y, y, x * x)));
    }
    __syncthreads();

    float sx, sy, sz, s2;
    {
        const float* c = coords + 3 * ((size_t)b * Nx + sample_idx(s));
        sx = c[0]; sy = c[1]; sz = c[2];
        s2 = fmaf(sz, sz, fmaf(sy, sy, sx * sx));
    }

    float held;
    int heldIdx = base + lane;
    {
        float4 p = sh[lane];
        held = fmaf(-2.0f, fmaf(sx, p.x, fmaf(sy, p.y, sz * p.z)), s2 + p.w);
    }
    float hmax;
    int maxlane;
    recompute_max(held, heldIdx, hmax, maxlane);

    for (int n0 = Kx; n0 < HALF; n0 += 32) {
        float4 p = sh[n0 + lane];
        float d = fmaf(-2.0f, fmaf(sx, p.x, fmaf(sy, p.y, sz * p.z)), s2 + p.w);
        unsigned qm = __ballot_sync(0xffffffffu, d < hmax);
        while (qm) {
            int src = __ffs(qm) - 1;
            qm &= qm - 1;
            float v = __shfl_sync(0xffffffffu, d, src);
            if (v < hmax) {
                if (lane == maxlane) { held = v; heldIdx = base + n0 + src; }
                recompute_max(held, heldIdx, hmax, maxlane);
            }
        }
    }

    unsigned hk = ordf(held);
    g_part[((size_t)(b * Sx + s) * 2 + half) * Kx + lane] =
        ((unsigned long long)hk << 32) | (unsigned)heldIdx;
}

// ---------------------------------------------------------------------------
// Kernel 2: merge partial top-32 sets; writes sampled output (unchanged)
// ---------------------------------------------------------------------------
__global__ __launch_bounds__(512, 2) void knn_merge_kernel(
    const float* __restrict__ coords, float* __restrict__ out_sampled) {
    int q = blockIdx.x * 16 + (threadIdx.x >> 5);
    int lane = threadIdx.x & 31;

    const unsigned long long* part = g_part + (size_t)q * 2 * Kx;
    unsigned long long a = part[lane];
    unsigned long long bb = part[32 + lane];

#pragma unroll
    for (int k = 2; k <= 64; k <<= 1) {
#pragma unroll
        for (int j = k >> 1; j > 0; j >>= 1) {
            if (j >= 32) {
                unsigned long long lo = a < bb ? a : bb;
                unsigned long long hi = a < bb ? bb : a;
                a = lo; bb = hi;
            } else {
                unsigned long long pa = __shfl_xor_sync(0xffffffffu, a, j);
                unsigned long long pb = __shfl_xor_sync(0xffffffffu, bb, j);
                bool lower = ((lane & j) == 0);
                bool upA = ((lane & k) == 0) || (k == 64);
                bool upB = (((lane + 32) & k) == 0) || (k == 64);
                bool keepMinA = (lower == upA);
                bool keepMinB = (lower == upB);
                a  = keepMinA ? (a  < pa ? a  : pa) : (a  > pa ? a  : pa);
                bb = keepMinB ? (bb < pb ? bb : pb) : (bb > pb ? bb : pb);
            }
        }
    }
    g_knn[(size_t)q * Kx + lane] = (int)(a & 0xffffffffu);

    int t = blockIdx.x * 512 + threadIdx.x;
    if (t < Bx * Sx * 3) {
        int idx = t / 3, comp = t - idx * 3;
        int b2 = idx >> 11, s2i = idx & 2047;
        out_sampled[t] = coords[3 * ((size_t)b2 * Nx + sample_idx(s2i)) + comp];
    }
}

// ---------------------------------------------------------------------------
// Kernel 3: tensor-core MLP via mma.sync tf32 (3xTF32 split).
// Persistent 148 CTAs x 256 thr. Tile = 4 groups = M128 x N128; 8 warps,
// each warp: 16 rows x 128 cols (64 fp32 acc regs).
// smem (f32, stride 136 = conflict-free frag loads):
//   A/H union [128][136], W1 [72][136], W2 [128][136], b1, b2, pool[8][128][2]
// ---------------------------------------------------------------------------
#define STR 136
#define OFF_A   0
#define OFF_W1  (128 * STR)                 /* 17408 */
#define OFF_W2  (OFF_W1 + 72 * STR)         /* 27200 */
#define OFF_B1  (OFF_W2 + 128 * STR)        /* 44608 */
#define OFF_B2  (OFF_B1 + 128)
#define OFF_PL  (OFF_B2 + 128)              /* 44864 */
#define SMEM_MLP ((OFF_PL + 8 * 128 * 2) * 4)  /* 187648 bytes */
#define NTILES (Bx * Sx / 4)

__global__ __launch_bounds__(256, 1) void mlp_tc_kernel(
    const float* __restrict__ coords,
    const float* __restrict__ features,
    const float* __restrict__ W1, const float* __restrict__ b1,
    const float* __restrict__ W2, const float* __restrict__ b2,
    float* __restrict__ out_pooled) {
    extern __shared__ float sm[];
    float* As  = sm + OFF_A;    // A1 (72 rows used) / H (128 rows), [c][j]
    float* W1s = sm + OFF_W1;   // [c][d], c<72 (67..71 zero)
    float* W2s = sm + OFF_W2;   // [c][d]
    float* b1s = sm + OFF_B1;
    float* b2s = sm + OFF_B2;
    float* pool = sm + OFF_PL;  // [warp][col][2] = max, min

    int tid = threadIdx.x;
    int wm = tid >> 5;          // warp 0..7, rows j0 = wm*16
    int lane = tid & 31;
    int g = lane >> 2;          // 0..7
    int t4 = lane & 3;          // 0..3

    // Stage weights (once per CTA)
    for (int i = tid; i < 72 * 128; i += 256) {
        int c = i >> 7, d = i & 127;
        W1s[c * STR + d] = (c < 67) ? W1[c * Dx + d] : 0.0f;
    }
    for (int i = tid; i < 128 * 128; i += 256) {
        int c = i >> 7, d = i & 127;
        W2s[c * STR + d] = W2[c * Dx + d];
    }
    if (tid < 128) { b1s[tid] = b1[tid]; b2s[tid] = b2[tid]; }
    __syncthreads();

    int j0 = wm * 16;

    for (int tile = blockIdx.x; tile < NTILES; tile += gridDim.x) {
        // ---- Gather A1[c][j]: c 0-2 rel, 3-66 features, 67-71 zero ----
        {
            int j = tid & 127;
            int hf = tid >> 7;
            int group = tile * 4 + (j >> 5);
            int b = group >> 11, s = group & 2047;
            int ni = g_knn[(size_t)group * Kx + (j & 31)];
            const float4* f4 =
                (const float4*)(features + ((size_t)b * Nx + ni) * Cx);
            if (hf == 0) {
                const float* sc = coords + 3 * ((size_t)b * Nx + sample_idx(s));
                const float* pc = coords + 3 * ((size_t)b * Nx + ni);
                As[0 * STR + j] = pc[0] - sc[0];
                As[1 * STR + j] = pc[1] - sc[1];
                As[2 * STR + j] = pc[2] - sc[2];
#pragma unroll
                for (int q = 0; q < 8; q++) {
                    float4 v = f4[q];
                    int c = 3 + 4 * q;
                    As[(c + 0) * STR + j] = v.x;
                    As[(c + 1) * STR + j] = v.y;
                    As[(c + 2) * STR + j] = v.z;
                    As[(c + 3) * STR + j] = v.w;
                }
            } else {
#pragma unroll
                for (int q = 8; q < 16; q++) {
                    float4 v = f4[q];
                    int c = 3 + 4 * q;
                    As[(c + 0) * STR + j] = v.x;
                    As[(c + 1) * STR + j] = v.y;
                    As[(c + 2) * STR + j] = v.z;
                    As[(c + 3) * STR + j] = v.w;
                }
#pragma unroll
                for (int c = 67; c < 72; c++) As[c * STR + j] = 0.0f;
            }
        }
        __syncthreads();

        float acc[64];

        // ---- Layer 1: Z1 = A1 @ W1p, K=72 ----
#pragma unroll
        for (int i = 0; i < 64; i++) acc[i] = 0.0f;
        for (int k = 0; k < 9; k++) {
            int k0 = 8 * k;
            uint32_t ah[4], al[4];
            {
                float r0 = As[(k0 + t4) * STR + j0 + g];
                float r1 = As[(k0 + t4) * STR + j0 + g + 8];
                float r2 = As[(k0 + t4 + 4) * STR + j0 + g];
                float r3 = As[(k0 + t4 + 4) * STR + j0 + g + 8];
                tf32_split(r0, ah[0], al[0]);
                tf32_split(r1, ah[1], al[1]);
                tf32_split(r2, ah[2], al[2]);
                tf32_split(r3, ah[3], al[3]);
            }
#pragma unroll
            for (int n = 0; n < 16; n++) {
                int n0 = 8 * n;
                uint32_t bh[2], bl[2];
                float w0 = W1s[(k0 + t4) * STR + n0 + g];
                float w1 = W1s[(k0 + t4 + 4) * STR + n0 + g];
                tf32_split(w0, bh[0], bl[0]);
                tf32_split(w1, bh[1], bl[1]);
                mma_tf32(acc + 4 * n, ah, bh);
                mma_tf32(acc + 4 * n, ah, bl);
                mma_tf32(acc + 4 * n, al, bh);
            }
        }
        __syncthreads();   // all warps done reading A1 before H overwrite

        // ---- Epilogue 1: H[col][row] = gelu(z + b1[col]) ----
#pragma unroll
        for (int n = 0; n < 16; n++) {
            int c0 = 8 * n + 2 * t4;
            float bv0 = b1s[c0], bv1 = b1s[c0 + 1];
            As[(c0 + 0) * STR + j0 + g]     = gelu_f(acc[4 * n + 0] + bv0);
            As[(c0 + 1) * STR + j0 + g]     = gelu_f(acc[4 * n + 1] + bv1);
            As[(c0 + 0) * STR + j0 + g + 8] = gelu_f(acc[4 * n + 2] + bv0);
            As[(c0 + 1) * STR + j0 + g + 8] = gelu_f(acc[4 * n + 3] + bv1);
        }
        __syncthreads();

        // ---- Layer 2: Z2 = H @ W2, K=128 ----
#pragma unroll
        for (int i = 0; i < 64; i++) acc[i] = 0.0f;
        for (int k = 0; k < 16; k++) {
            int k0 = 8 * k;
            uint32_t ah[4], al[4];
            {
                float r0 = As[(k0 + t4) * STR + j0 + g];
                float r1 = As[(k0 + t4) * STR + j0 + g + 8];
                float r2 = As[(k0 + t4 + 4) * STR + j0 + g];
                float r3 = As[(k0 + t4 + 4) * STR + j0 + g + 8];
                tf32_split(r0, ah[0], al[0]);
                tf32_split(r1, ah[1], al[1]);
                tf32_split(r2, ah[2], al[2]);
                tf32_split(r3, ah[3], al[3]);
            }
#pragma unroll
            for (int n = 0; n < 16; n++) {
                int n0 = 8 * n;
                uint32_t bh[2], bl[2];
                float w0 = W2s[(k0 + t4) * STR + n0 + g];
                float w1 = W2s[(k0 + t4 + 4) * STR + n0 + g];
                tf32_split(w0, bh[0], bl[0]);
                tf32_split(w1, bh[1], bl[1]);
                mma_tf32(acc + 4 * n, ah, bh);
                mma_tf32(acc + 4 * n, ah, bl);
                mma_tf32(acc + 4 * n, al, bh);
            }
        }

        // ---- Epilogue 2: pool. Reduce 16 rows in-warp, combine via smem ----
#pragma unroll
        for (int n = 0; n < 16; n++) {
            float mx0 = fmaxf(acc[4 * n + 0], acc[4 * n + 2]);
            float mn0 = fminf(acc[4 * n + 0], acc[4 * n + 2]);
            float mx1 = fmaxf(acc[4 * n + 1], acc[4 * n + 3]);
            float mn1 = fminf(acc[4 * n + 1], acc[4 * n + 3]);
#pragma unroll
            for (int off = 4; off < 32; off <<= 1) {
                mx0 = fmaxf(mx0, __shfl_xor_sync(0xffffffffu, mx0, off));
                mn0 = fminf(mn0, __shfl_xor_sync(0xffffffffu, mn0, off));
                mx1 = fmaxf(mx1, __shfl_xor_sync(0xffffffffu, mx1, off));
                mn1 = fminf(mn1, __shfl_xor_sync(0xffffffffu, mn1, off));
            }
            if (g == 0) {
                int c0 = 8 * n + 2 * t4;
                pool[(wm * 128 + c0) * 2 + 0] = mx0;
                pool[(wm * 128 + c0) * 2 + 1] = mn0;
                pool[(wm * 128 + c0 + 1) * 2 + 0] = mx1;
                pool[(wm * 128 + c0 + 1) * 2 + 1] = mn1;
            }
        }
        __syncthreads();

        // Combine two warps per group; unimodal-gelu pool; write out
#pragma unroll
        for (int it = 0; it < 2; it++) {
            int item = tid + it * 256;     // 0..511
            int grp = item >> 7, col = item & 127;
            int wA = grp * 2, wB = grp * 2 + 1;
            float mx = fmaxf(pool[(wA * 128 + col) * 2 + 0],
                             pool[(wB * 128 + col) * 2 + 0]);
            float mn = fminf(pool[(wA * 128 + col) * 2 + 1],
                             pool[(wB * 128 + col) * 2 + 1]);
            float bv = b2s[col];
            out_pooled[(size_t)(tile * 4 + grp) * Dx + col] =
                fmaxf(gelu_f(mx + bv), gelu_f(mn + bv));
        }
        __syncthreads();   // protect A/H + pool before next iteration
    }
}

// ---------------------------------------------------------------------------
extern "C" void kernel_launch(void* const* d_in, const int* in_sizes, int n_in,
                              void* d_out, int out_size) {
    (void)in_sizes; (void)n_in; (void)out_size;
    const float* coords   = (const float*)d_in[0];
    const float* features = (const float*)d_in[1];
    const float* W1 = (const float*)d_in[2];
    const float* b1 = (const float*)d_in[3];
    const float* W2 = (const float*)d_in[4];
    const float* b2 = (const float*)d_in[5];

    float* out = (float*)d_out;
    float* out_sampled = out;                       // (B,S,3)
    float* out_pooled  = out + (size_t)Bx * Sx * 3; // (B,S,128)

    cudaFuncSetAttribute(knn_part_kernel,
                         cudaFuncAttributeMaxDynamicSharedMemorySize,
                         HALF * (int)sizeof(float4));
    knn_part_kernel<<<1024, 512, HALF * sizeof(float4)>>>(coords);

    knn_merge_kernel<<<512, 512>>>(coords, out_sampled);

    cudaFuncSetAttribute(mlp_tc_kernel,
                         cudaFuncAttributeMaxDynamicSharedMemorySize, SMEM_MLP);
    mlp_tc_kernel<<<148, 256, SMEM_MLP>>>(
        coords, features, W1, b1, W2, b2, out_pooled);
}

// round 12
// speedup vs baseline: 5.9431x; 1.4156x over previous
#include <cuda_runtime.h>
#include <cuda_bf16.h>
#include <math.h>
#include <stdint.h>

#define Bx 4
#define Nx 8192
#define Cx 64
#define Dx 128
#define Sx 2048
#define Kx 32
#define HALF 4096

// Scratch: partial top-32 keys per (query, half) and final knn indices
__device__ unsigned long long g_part[Bx * Sx * 2 * Kx];   // 4 MB
__device__ int g_knn[Bx * Sx * Kx];

// ---------------------------------------------------------------------------
// Math helpers
// ---------------------------------------------------------------------------
__device__ __forceinline__ float gelu_f(float x) {
    float z = fabsf(x) * 0.70710678118654752440f;
    float den = fmaf(0.3275911f, z, 1.0f);
    float t;
    asm("rcp.approx.f32 %0, %1;" : "=f"(t) : "f"(den));
    float poly = t * fmaf(t, fmaf(t, fmaf(t, fmaf(t, 1.061405429f, -1.453152027f),
                                          1.421413741f), -0.284496736f), 0.254829592f);
    float ex = __expf(-z * z);
    float e = fmaf(-poly, ex, 1.0f);
    float s = copysignf(e, x);
    return 0.5f * x * (1.0f + s);
}

__device__ __forceinline__ int sample_idx(int s) {
    float q = __fdiv_rn((float)s, 2047.0f);
    return __float2int_rn(__fmul_rn(8191.0f, q));
}

__device__ __forceinline__ unsigned ordf(float f) {
    unsigned u = __float_as_uint(f);
    return u ^ ((u >> 31) ? 0xffffffffu : 0x80000000u);
}

// bf16 hi/lo split of two floats -> packed hi-word and lo-word (x1 in upper half)
__device__ __forceinline__ void split_pack2(float x0, float x1,
                                            uint32_t& hw, uint32_t& lw) {
    __nv_bfloat16 h0 = __float2bfloat16_rn(x0);
    __nv_bfloat16 h1 = __float2bfloat16_rn(x1);
    __nv_bfloat16 l0 = __float2bfloat16_rn(x0 - __bfloat162float(h0));
    __nv_bfloat16 l1 = __float2bfloat16_rn(x1 - __bfloat162float(h1));
    hw = ((uint32_t)__bfloat16_as_ushort(h1) << 16) | __bfloat16_as_ushort(h0);
    lw = ((uint32_t)__bfloat16_as_ushort(l1) << 16) | __bfloat16_as_ushort(l0);
}

// m16n8k16 bf16 mma, acc in-place
__device__ __forceinline__ void mma_bf16(float* c, const uint32_t* a,
                                         const uint32_t* b) {
    asm volatile(
        "mma.sync.aligned.m16n8k16.row.col.f32.bf16.bf16.f32 "
        "{%0,%1,%2,%3}, {%4,%5,%6,%7}, {%8,%9}, {%0,%1,%2,%3};"
        : "+f"(c[0]), "+f"(c[1]), "+f"(c[2]), "+f"(c[3])
        : "r"(a[0]), "r"(a[1]), "r"(a[2]), "r"(a[3]), "r"(b[0]), "r"(b[1]));
}

__device__ __forceinline__ void recompute_max(float held, int heldIdx,
                                              float& hmax, int& maxlane) {
    unsigned hk = ordf(held);
    unsigned mk = __reduce_max_sync(0xffffffffu, hk);
    unsigned mm = __ballot_sync(0xffffffffu, hk == mk);
    if (__popc(mm) > 1) {
        unsigned cand = (hk == mk) ? (unsigned)heldIdx : 0u;
        unsigned mi = __reduce_max_sync(0xffffffffu, cand);
        mm = __ballot_sync(0xffffffffu, (hk == mk) && ((unsigned)heldIdx == mi));
    }
    maxlane = __ffs(mm) - 1;
    hmax = __shfl_sync(0xffffffffu, held, maxlane);
}

// ---------------------------------------------------------------------------
// Kernel 1: partial kNN (unchanged, 136 us measured)
// ---------------------------------------------------------------------------
__global__ __launch_bounds__(512, 2) void knn_part_kernel(
    const float* __restrict__ coords) {
    extern __shared__ float4 sh[];
    int blk = blockIdx.x;
    int half = blk & 1;
    int qg = blk >> 1;
    int b = qg >> 7;
    int warp = threadIdx.x >> 5;
    int s = ((qg & 127) << 4) + warp;
    int lane = threadIdx.x & 31;
    int base = half * HALF;

    for (int i = threadIdx.x; i < HALF; i += 512) {
        const float* c = coords + 3 * ((size_t)b * Nx + base + i);
        float x = c[0], y = c[1], z = c[2];
        sh[i] = make_float4(x, y, z, fmaf(z, z, fmaf(y, y, x * x)));
    }
    __syncthreads();

    float sx, sy, sz, s2;
    {
        const float* c = coords + 3 * ((size_t)b * Nx + sample_idx(s));
        sx = c[0]; sy = c[1]; sz = c[2];
        s2 = fmaf(sz, sz, fmaf(sy, sy, sx * sx));
    }

    float held;
    int heldIdx = base + lane;
    {
        float4 p = sh[lane];
        held = fmaf(-2.0f, fmaf(sx, p.x, fmaf(sy, p.y, sz * p.z)), s2 + p.w);
    }
    float hmax;
    int maxlane;
    recompute_max(held, heldIdx, hmax, maxlane);

    for (int n0 = Kx; n0 < HALF; n0 += 32) {
        float4 p = sh[n0 + lane];
        float d = fmaf(-2.0f, fmaf(sx, p.x, fmaf(sy, p.y, sz * p.z)), s2 + p.w);
        unsigned qm = __ballot_sync(0xffffffffu, d < hmax);
        while (qm) {
            int src = __ffs(qm) - 1;
            qm &= qm - 1;
            float v = __shfl_sync(0xffffffffu, d, src);
            if (v < hmax) {
                if (lane == maxlane) { held = v; heldIdx = base + n0 + src; }
                recompute_max(held, heldIdx, hmax, maxlane);
            }
        }
    }

    unsigned hk = ordf(held);
    g_part[((size_t)(b * Sx + s) * 2 + half) * Kx + lane] =
        ((unsigned long long)hk << 32) | (unsigned)heldIdx;
}

// ---------------------------------------------------------------------------
// Kernel 2: merge partial top-32 sets; writes sampled output (unchanged)
// ---------------------------------------------------------------------------
__global__ __launch_bounds__(512, 2) void knn_merge_kernel(
    const float* __restrict__ coords, float* __restrict__ out_sampled) {
    int q = blockIdx.x * 16 + (threadIdx.x >> 5);
    int lane = threadIdx.x & 31;

    const unsigned long long* part = g_part + (size_t)q * 2 * Kx;
    unsigned long long a = part[lane];
    unsigned long long bb = part[32 + lane];

#pragma unroll
    for (int k = 2; k <= 64; k <<= 1) {
#pragma unroll
        for (int j = k >> 1; j > 0; j >>= 1) {
            if (j >= 32) {
                unsigned long long lo = a < bb ? a : bb;
                unsigned long long hi = a < bb ? bb : a;
                a = lo; bb = hi;
            } else {
                unsigned long long pa = __shfl_xor_sync(0xffffffffu, a, j);
                unsigned long long pb = __shfl_xor_sync(0xffffffffu, bb, j);
                bool lower = ((lane & j) == 0);
                bool upA = ((lane & k) == 0) || (k == 64);
                bool upB = (((lane + 32) & k) == 0) || (k == 64);
                bool keepMinA = (lower == upA);
                bool keepMinB = (lower == upB);
                a  = keepMinA ? (a  < pa ? a  : pa) : (a  > pa ? a  : pa);
                bb = keepMinB ? (bb < pb ? bb : pb) : (bb > pb ? bb : pb);
            }
        }
    }
    g_knn[(size_t)q * Kx + lane] = (int)(a & 0xffffffffu);

    int t = blockIdx.x * 512 + threadIdx.x;
    if (t < Bx * Sx * 3) {
        int idx = t / 3, comp = t - idx * 3;
        int b2 = idx >> 11, s2i = idx & 2047;
        out_sampled[t] = coords[3 * ((size_t)b2 * Nx + sample_idx(s2i)) + comp];
    }
}

// ---------------------------------------------------------------------------
// Kernel 3: MLP via mma.sync m16n8k16 bf16 (hi/lo 3-way split, pre-split
// packed operands). Persistent 148 CTAs x 256 thr. Tile = 4 groups = M128xN128.
// smem layout in u32 words; pair-of-bf16 per word; row stride 136 words
// (bank = 8*t4 + g, conflict-free).
//   Ah[64][136] Al[64][136]  (A1 uses kw 0..39, H uses 0..63)
//   W1h[40][136] W1l[40][136] W2h[64][136] W2l[64][136]
//   b1[128] b2[128] pool[8][128][2]
// ---------------------------------------------------------------------------
#define STRW 136
#define OFF_AH  0
#define OFF_AL  (64 * STRW)                    /* 8704 */
#define OFF_W1H (OFF_AL + 64 * STRW)           /* 17408 */
#define OFF_W1L (OFF_W1H + 40 * STRW)          /* 22848 */
#define OFF_W2H (OFF_W1L + 40 * STRW)          /* 28288 */
#define OFF_W2L (OFF_W2H + 64 * STRW)          /* 36992 */
#define OFF_B1  (OFF_W2L + 64 * STRW)          /* 45696 */
#define OFF_B2  (OFF_B1 + 128)
#define OFF_PL  (OFF_B2 + 128)                 /* 45952 */
#define SMEM_MLP ((OFF_PL + 8 * 128 * 2) * 4)  /* 192000 bytes */
#define NTILES (Bx * Sx / 4)

__global__ __launch_bounds__(256, 1) void mlp_tc_kernel(
    const float* __restrict__ coords,
    const float* __restrict__ features,
    const float* __restrict__ W1, const float* __restrict__ b1,
    const float* __restrict__ W2, const float* __restrict__ b2,
    float* __restrict__ out_pooled) {
    extern __shared__ uint32_t smu[];
    uint32_t* Ah  = smu + OFF_AH;
    uint32_t* Al  = smu + OFF_AL;
    uint32_t* W1h = smu + OFF_W1H;
    uint32_t* W1l = smu + OFF_W1L;
    uint32_t* W2h = smu + OFF_W2H;
    uint32_t* W2l = smu + OFF_W2L;
    float* b1s = (float*)(smu + OFF_B1);
    float* b2s = (float*)(smu + OFF_B2);
    float* pool = (float*)(smu + OFF_PL);

    int tid = threadIdx.x;
    int wm = tid >> 5;          // warp 0..7, rows j0 = wm*16
    int lane = tid & 31;
    int g = lane >> 2;          // 0..7
    int t4 = lane & 3;          // 0..3
    int j0 = wm * 16;

    // Stage weights pre-split (once per CTA). Channel order c: 0-2 rel,
    // 3-66 features (W1 rows directly), 67-79 zero pad.
    for (int i = tid; i < 40 * 128; i += 256) {
        int kw = i >> 7, d = i & 127;
        int c0 = 2 * kw, c1 = 2 * kw + 1;
        float w0 = (c0 < 67) ? W1[c0 * Dx + d] : 0.0f;
        float w1 = (c1 < 67) ? W1[c1 * Dx + d] : 0.0f;
        uint32_t hw, lw;
        split_pack2(w0, w1, hw, lw);
        W1h[kw * STRW + d] = hw;
        W1l[kw * STRW + d] = lw;
    }
    for (int i = tid; i < 64 * 128; i += 256) {
        int kw = i >> 7, d = i & 127;
        float w0 = W2[(2 * kw) * Dx + d];
        float w1 = W2[(2 * kw + 1) * Dx + d];
        uint32_t hw, lw;
        split_pack2(w0, w1, hw, lw);
        W2h[kw * STRW + d] = hw;
        W2l[kw * STRW + d] = lw;
    }
    if (tid < 128) { b1s[tid] = b1[tid]; b2s[tid] = b2[tid]; }
    __syncthreads();

    for (int tile = blockIdx.x; tile < NTILES; tile += gridDim.x) {
        // ---- Gather A1 pre-split: row j = tid&127; hf=0 -> c 0..39,
        //      hf=1 -> c 40..79 (feats 37..63 + zero pad) ----
        {
            int j = tid & 127;
            int hf = tid >> 7;
            int group = tile * 4 + (j >> 5);
            int b = group >> 11, s = group & 2047;
            int ni = g_knn[(size_t)group * Kx + (j & 31)];
            const float4* f4 =
                (const float4*)(features + ((size_t)b * Nx + ni) * Cx);
            float va[40];
            if (hf == 0) {
                const float* sc = coords + 3 * ((size_t)b * Nx + sample_idx(s));
                const float* pc = coords + 3 * ((size_t)b * Nx + ni);
                va[0] = pc[0] - sc[0];
                va[1] = pc[1] - sc[1];
                va[2] = pc[2] - sc[2];
                float tf[40];
#pragma unroll
                for (int q = 0; q < 10; q++) {
                    float4 v = f4[q];
                    tf[4 * q] = v.x; tf[4 * q + 1] = v.y;
                    tf[4 * q + 2] = v.z; tf[4 * q + 3] = v.w;
                }
#pragma unroll
                for (int u = 0; u < 37; u++) va[3 + u] = tf[u];
            } else {
                float tf[28];
#pragma unroll
                for (int q = 0; q < 7; q++) {
                    float4 v = f4[9 + q];          // feats 36..63
                    tf[4 * q] = v.x; tf[4 * q + 1] = v.y;
                    tf[4 * q + 2] = v.z; tf[4 * q + 3] = v.w;
                }
#pragma unroll
                for (int u = 0; u < 27; u++) va[u] = tf[1 + u];  // feats 37..63
#pragma unroll
                for (int u = 27; u < 40; u++) va[u] = 0.0f;
            }
#pragma unroll
            for (int kw = 0; kw < 20; kw++) {
                uint32_t hw, lw;
                split_pack2(va[2 * kw], va[2 * kw + 1], hw, lw);
                int kwg = 20 * hf + kw;
                Ah[kwg * STRW + j] = hw;
                Al[kwg * STRW + j] = lw;
            }
        }
        __syncthreads();

        float acc[64];

        // ---- Layer 1: Z1 = A1 @ W1, K=80 (5 k16 iters, 3 MMAs each) ----
#pragma unroll
        for (int i = 0; i < 64; i++) acc[i] = 0.0f;
#pragma unroll
        for (int k = 0; k < 5; k++) {
            int kw0 = 8 * k;
            uint32_t ah[4], al[4];
            ah[0] = Ah[(kw0 + t4) * STRW + j0 + g];
            ah[1] = Ah[(kw0 + t4) * STRW + j0 + 8 + g];
            ah[2] = Ah[(kw0 + t4 + 4) * STRW + j0 + g];
            ah[3] = Ah[(kw0 + t4 + 4) * STRW + j0 + 8 + g];
            al[0] = Al[(kw0 + t4) * STRW + j0 + g];
            al[1] = Al[(kw0 + t4) * STRW + j0 + 8 + g];
            al[2] = Al[(kw0 + t4 + 4) * STRW + j0 + g];
            al[3] = Al[(kw0 + t4 + 4) * STRW + j0 + 8 + g];
#pragma unroll
            for (int n = 0; n < 16; n++) {
                int n0 = 8 * n;
                uint32_t bh[2], bl[2];
                bh[0] = W1h[(kw0 + t4) * STRW + n0 + g];
                bh[1] = W1h[(kw0 + t4 + 4) * STRW + n0 + g];
                bl[0] = W1l[(kw0 + t4) * STRW + n0 + g];
                bl[1] = W1l[(kw0 + t4 + 4) * STRW + n0 + g];
                mma_bf16(acc + 4 * n, ah, bh);
                mma_bf16(acc + 4 * n, ah, bl);
                mma_bf16(acc + 4 * n, al, bh);
            }
        }
        __syncthreads();   // all warps done reading A1 before H overwrite

        // ---- Epilogue 1: H = gelu(z + b1), re-split into Ah/Al (kw 0..63) ----
#pragma unroll
        for (int n = 0; n < 16; n++) {
            int c0 = 8 * n + 2 * t4;
            int kw = 4 * n + t4;
            float bv0 = b1s[c0], bv1 = b1s[c0 + 1];
            uint32_t hw, lw;
            split_pack2(gelu_f(acc[4 * n + 0] + bv0),
                        gelu_f(acc[4 * n + 1] + bv1), hw, lw);
            Ah[kw * STRW + j0 + g] = hw;
            Al[kw * STRW + j0 + g] = lw;
            split_pack2(gelu_f(acc[4 * n + 2] + bv0),
                        gelu_f(acc[4 * n + 3] + bv1), hw, lw);
            Ah[kw * STRW + j0 + 8 + g] = hw;
            Al[kw * STRW + j0 + 8 + g] = lw;
        }
        __syncthreads();

        // ---- Layer 2: Z2 = H @ W2, K=128 (8 k16 iters) ----
#pragma unroll
        for (int i = 0; i < 64; i++) acc[i] = 0.0f;
#pragma unroll
        for (int k = 0; k < 8; k++) {
            int kw0 = 8 * k;
            uint32_t ah[4], al[4];
            ah[0] = Ah[(kw0 + t4) * STRW + j0 + g];
            ah[1] = Ah[(kw0 + t4) * STRW + j0 + 8 + g];
            ah[2] = Ah[(kw0 + t4 + 4) * STRW + j0 + g];
            ah[3] = Ah[(kw0 + t4 + 4) * STRW + j0 + 8 + g];
            al[0] = Al[(kw0 + t4) * STRW + j0 + g];
            al[1] = Al[(kw0 + t4) * STRW + j0 + 8 + g];
            al[2] = Al[(kw0 + t4 + 4) * STRW + j0 + g];
            al[3] = Al[(kw0 + t4 + 4) * STRW + j0 + 8 + g];
#pragma unroll
            for (int n = 0; n < 16; n++) {
                int n0 = 8 * n;
                uint32_t bh[2], bl[2];
                bh[0] = W2h[(kw0 + t4) * STRW + n0 + g];
                bh[1] = W2h[(kw0 + t4 + 4) * STRW + n0 + g];
                bl[0] = W2l[(kw0 + t4) * STRW + n0 + g];
                bl[1] = W2l[(kw0 + t4 + 4) * STRW + n0 + g];
                mma_bf16(acc + 4 * n, ah, bh);
                mma_bf16(acc + 4 * n, ah, bl);
                mma_bf16(acc + 4 * n, al, bh);
            }
        }

        // ---- Epilogue 2: pool (unimodal gelu: only max/min of z needed) ----
#pragma unroll
        for (int n = 0; n < 16; n++) {
            float mx0 = fmaxf(acc[4 * n + 0], acc[4 * n + 2]);
            float mn0 = fminf(acc[4 * n + 0], acc[4 * n + 2]);
            float mx1 = fmaxf(acc[4 * n + 1], acc[4 * n + 3]);
            float mn1 = fminf(acc[4 * n + 1], acc[4 * n + 3]);
#pragma unroll
            for (int off = 4; off < 32; off <<= 1) {
                mx0 = fmaxf(mx0, __shfl_xor_sync(0xffffffffu, mx0, off));
                mn0 = fminf(mn0, __shfl_xor_sync(0xffffffffu, mn0, off));
                mx1 = fmaxf(mx1, __shfl_xor_sync(0xffffffffu, mx1, off));
                mn1 = fminf(mn1, __shfl_xor_sync(0xffffffffu, mn1, off));
            }
            if (g == 0) {
                int c0 = 8 * n + 2 * t4;
                pool[(wm * 128 + c0) * 2 + 0] = mx0;
                pool[(wm * 128 + c0) * 2 + 1] = mn0;
                pool[(wm * 128 + c0 + 1) * 2 + 0] = mx1;
                pool[(wm * 128 + c0 + 1) * 2 + 1] = mn1;
            }
        }
        __syncthreads();

#pragma unroll
        for (int it = 0; it < 2; it++) {
            int item = tid + it * 256;     // 0..511
            int grp = item >> 7, col = item & 127;
            int wA = grp * 2, wB = grp * 2 + 1;
            float mx = fmaxf(pool[(wA * 128 + col) * 2 + 0],
                             pool[(wB * 128 + col) * 2 + 0]);
            float mn = fminf(pool[(wA * 128 + col) * 2 + 1],
                             pool[(wB * 128 + col) * 2 + 1]);
            float bv = b2s[col];
            out_pooled[(size_t)(tile * 4 + grp) * Dx + col] =
                fmaxf(gelu_f(mx + bv), gelu_f(mn + bv));
        }
        __syncthreads();   // protect Ah/Al + pool before next tile
    }
}

// ---------------------------------------------------------------------------
extern "C" void kernel_launch(void* const* d_in, const int* in_sizes, int n_in,
                              void* d_out, int out_size) {
    (void)in_sizes; (void)n_in; (void)out_size;
    const float* coords   = (const float*)d_in[0];
    const float* features = (const float*)d_in[1];
    const float* W1 = (const float*)d_in[2];
    const float* b1 = (const float*)d_in[3];
    const float* W2 = (const float*)d_in[4];
    const float* b2 = (const float*)d_in[5];

    float* out = (float*)d_out;
    float* out_sampled = out;                       // (B,S,3)
    float* out_pooled  = out + (size_t)Bx * Sx * 3; // (B,S,128)

    cudaFuncSetAttribute(knn_part_kernel,
                         cudaFuncAttributeMaxDynamicSharedMemorySize,
                         HALF * (int)sizeof(float4));
    knn_part_kernel<<<1024, 512, HALF * sizeof(float4)>>>(coords);

    knn_merge_kernel<<<512, 512>>>(coords, out_sampled);

    cudaFuncSetAttribute(mlp_tc_kernel,
                         cudaFuncAttributeMaxDynamicSharedMemorySize, SMEM_MLP);
    mlp_tc_kernel<<<148, 256, SMEM_MLP>>>(
        coords, features, W1, b1, W2, b2, out_pooled);
}